// round 12
// baseline (speedup 1.0000x reference)
#include <cuda_runtime.h>

// ---------------------------------------------------------------------------
// NeuralSplineFlow3D — fp32 FFMA2, R8 per-thread shape (4 pts x 16 outs),
// CTA shrunk to 128 pts / 128 thr, weights staged 2-layers-at-a-time
// -> ~102 KB smem -> 2 CTAs/SM (decoupled barriers, phase overlap).
// ---------------------------------------------------------------------------

#define THREADS   128
#define COLS      128
#define PW        68
#define PO        80
#define TBc       5.0f
#define MINc      0.001f
#define LOGZc     (-2.7568155996140194f)
#define DCONSTf   (0.5397424697f)

// smem layout (float offsets)
#define SM_WT     0                      // 2*64*68 = 8704 (also holds Wo 64*80=5120)
#define SM_WIN    8704                   // 64
#define SM_BIN    8768                   // 64
#define SM_BBLK   8832                   // 256
#define SM_BOUT   9088                   // 80
#define SM_H      9168                   // 64*128 = 8192
#define SM_T      (SM_H + 8192)          // 8192
#define SM_TOTALF (SM_T + 8192)          // 25552
#define SMEM_BYTES (SM_TOTALF * 4)       // 102208 B -> 2 CTAs/SM

typedef unsigned long long u64;

static __device__ __forceinline__ u64 ffma2(u64 a, u64 b, u64 c) {
    u64 d;
    asm("fma.rn.f32x2 %0, %1, %2, %3;" : "=l"(d) : "l"(a), "l"(b), "l"(c));
    return d;
}
static __device__ __forceinline__ u64 pk2(float v) {
    u64 r;
    asm("mov.b64 %0, {%1, %1};" : "=l"(r) : "f"(v));
    return r;
}
static __device__ __forceinline__ void upk2(u64 v, float& lo, float& hi) {
    asm("mov.b64 {%0, %1}, %2;" : "=f"(lo), "=f"(hi) : "l"(v));
}
static __device__ __forceinline__ float softplusf(float x) {
    return fmaxf(x, 0.0f) + log1pf(__expf(-fabsf(x)));
}

// ---- hidden dense layer: thread = 4 pts x 16 outs (R8 k-loop, 128-col rows) -
template<bool ADD>
static __device__ __forceinline__ void dense_tile(const float* __restrict__ Wt,
                                                  const float* __restrict__ bias,
                                                  const float* __restrict__ inb,
                                                  float* __restrict__ dst,
                                                  int tx, int ty) {
    const int ob = 16 * ty;
    u64 acc[4][8];
#pragma unroll
    for (int q = 0; q < 8; ++q) {
        u64 b = *reinterpret_cast<const u64*>(bias + ob + 2 * q);
        acc[0][q] = b; acc[1][q] = b; acc[2][q] = b; acc[3][q] = b;
    }
    const float* cp = inb + 4 * tx;
#pragma unroll 2
    for (int k = 0; k < 64; ++k) {
        float4 a = *reinterpret_cast<const float4*>(cp + (k << 7));
        u64 r0 = pk2(fmaxf(a.x, 0.0f));
        u64 r1 = pk2(fmaxf(a.y, 0.0f));
        u64 r2 = pk2(fmaxf(a.z, 0.0f));
        u64 r3 = pk2(fmaxf(a.w, 0.0f));
        const float* wr = Wt + k * PW + ob;
#pragma unroll
        for (int q2 = 0; q2 < 4; ++q2) {
            ulonglong2 w = *reinterpret_cast<const ulonglong2*>(wr + 4 * q2);
            acc[0][2 * q2]     = ffma2(r0, w.x, acc[0][2 * q2]);
            acc[1][2 * q2]     = ffma2(r1, w.x, acc[1][2 * q2]);
            acc[2][2 * q2]     = ffma2(r2, w.x, acc[2][2 * q2]);
            acc[3][2 * q2]     = ffma2(r3, w.x, acc[3][2 * q2]);
            acc[0][2 * q2 + 1] = ffma2(r0, w.y, acc[0][2 * q2 + 1]);
            acc[1][2 * q2 + 1] = ffma2(r1, w.y, acc[1][2 * q2 + 1]);
            acc[2][2 * q2 + 1] = ffma2(r2, w.y, acc[2][2 * q2 + 1]);
            acc[3][2 * q2 + 1] = ffma2(r3, w.y, acc[3][2 * q2 + 1]);
        }
    }
#pragma unroll
    for (int q = 0; q < 8; ++q) {
        float l0, h0, l1, h1, l2, h2, l3, h3;
        upk2(acc[0][q], l0, h0); upk2(acc[1][q], l1, h1);
        upk2(acc[2][q], l2, h2); upk2(acc[3][q], l3, h3);
        float4 vlo = make_float4(l0, l1, l2, l3);
        float4 vhi = make_float4(h0, h1, h2, h3);
        float* d0 = dst + ((ob + 2 * q) << 7) + 4 * tx;
        float* d1 = dst + ((ob + 2 * q + 1) << 7) + 4 * tx;
        if (ADD) {
            float4 e0 = *reinterpret_cast<const float4*>(d0);
            float4 e1 = *reinterpret_cast<const float4*>(d1);
            vlo.x += e0.x; vlo.y += e0.y; vlo.z += e0.z; vlo.w += e0.w;
            vhi.x += e1.x; vhi.y += e1.y; vhi.z += e1.z; vhi.w += e1.w;
        }
        *reinterpret_cast<float4*>(d0) = vlo;
        *reinterpret_cast<float4*>(d1) = vhi;
    }
}

// stage one PAIR of hidden layers (8192 floats) transposed into sWt
static __device__ __forceinline__ void stage_pair(float* __restrict__ sWt,
                                                  const float* __restrict__ gW2,
                                                  int tid) {
    for (int idx = tid; idx < 8192; idx += THREADS) {
        int l = idx >> 12, rem = idx & 4095, o = rem >> 6, k = rem & 63;
        sWt[(l * 64 + k) * PW + o] = gW2[idx];
    }
}

extern "C" __global__ void __launch_bounds__(THREADS, 2)
nsf_kernel(const float* __restrict__ x,
           const float* __restrict__ W_in,  const float* __restrict__ b_in,
           const float* __restrict__ W_blk, const float* __restrict__ b_blk,
           const float* __restrict__ W_out, const float* __restrict__ b_out,
           float* __restrict__ out, int n) {
    extern __shared__ float sm[];
    float* sWt  = sm + SM_WT;          // hidden pair OR out weights (time-shared)
    float* sWin = sm + SM_WIN;
    float* sbin = sm + SM_BIN;
    float* sbb  = sm + SM_BBLK;
    float* sbo  = sm + SM_BOUT;
    float* sh   = sm + SM_H;
    float* st   = sm + SM_T;

    const int tid = threadIdx.x;
    const int tx  = tid & 31;
    const int ty  = tid >> 5;

    const int gidr = blockIdx.x * COLS + tid;
    const bool valid = (gidr < n);
    const int g = valid ? gidr : (n - 1);

    float z0 = x[3 * g + 0];
    float z1 = x[3 * g + 1];
    float z2 = x[3 * g + 2];
    float lad_total = 0.0f;

    for (int it = 0; it < 8; ++it) {
        __syncthreads();   // prev transform done with sWt/panels/consts

        // ---- stage layers 0,1 + small consts ----
        stage_pair(sWt, W_blk + it * 16384, tid);
        if (tid < 64) {
            sWin[tid] = W_in[it * 64 + tid];
            sbin[tid] = b_in[it * 64 + tid];
        }
        for (int idx = tid; idx < 256; idx += THREADS)
            sbb[idx] = b_blk[it * 256 + idx];
        if (tid < 74) {
            int col = (tid < 37) ? tid : (tid + 3);
            sbo[col] = b_out[it * 74 + tid];
        }
        if (tid >= 74 && tid < 80) {
            int pc = tid - 74;
            int col = (pc < 3) ? (37 + pc) : (74 + pc);
            sbo[col] = 0.0f;
        }
        __syncthreads();

        float c = z2, t0 = z1, t1 = z0;

        // h = ident * W_in + b_in  (thread owns column tid)
#pragma unroll 8
        for (int o = 0; o < 64; ++o)
            sh[(o << 7) + tid] = fmaf(c, sWin[o], sbin[o]);
        __syncthreads();

        // ---- residual block 1 ----
        dense_tile<false>(sWt,           sbb,      sh, st, tx, ty); __syncthreads();
        dense_tile<true >(sWt + 64 * PW, sbb + 64, st, sh, tx, ty); __syncthreads();

        // ---- stage layers 2,3 (sWt dead, st dead) ----
        stage_pair(sWt, W_blk + it * 16384 + 8192, tid);
        __syncthreads();

        // ---- residual block 2 ----
        dense_tile<false>(sWt,           sbb + 128, sh, st, tx, ty); __syncthreads();
        dense_tile<true >(sWt + 64 * PW, sbb + 192, st, sh, tx, ty); __syncthreads();

        // ---- stage out weights into sWt (padded cols, pitch PO) ----
        {
            const float* gWo = W_out + it * 74 * 64;
            for (int idx = tid; idx < 74 * 64; idx += THREADS) {
                int o = idx >> 6, k = idx & 63;
                int col = (o < 37) ? o : (o + 3);
                sWt[k * PO + col] = gWo[idx];
            }
            for (int idx = tid; idx < 6 * 64; idx += THREADS) {
                int pc = idx % 6, k = idx / 6;
                int col = (pc < 3) ? (37 + pc) : (74 + pc);
                sWt[k * PO + col] = 0.0f;
            }
        }
        __syncthreads();

        // ---- output layer: thread = 4 pts x 20 param cols ----
        {
            const int ob = 20 * ty;
            u64 acc[4][10];
#pragma unroll
            for (int q = 0; q < 10; ++q) {
                u64 b = *reinterpret_cast<const u64*>(sbo + ob + 2 * q);
                acc[0][q] = b; acc[1][q] = b; acc[2][q] = b; acc[3][q] = b;
            }
            const float* cp = sh + 4 * tx;
#pragma unroll 2
            for (int k = 0; k < 64; ++k) {
                float4 a = *reinterpret_cast<const float4*>(cp + (k << 7));
                u64 r0 = pk2(a.x), r1 = pk2(a.y), r2 = pk2(a.z), r3 = pk2(a.w);
                const float* wr = sWt + k * PO + ob;
#pragma unroll
                for (int q2 = 0; q2 < 5; ++q2) {
                    ulonglong2 w = *reinterpret_cast<const ulonglong2*>(wr + 4 * q2);
                    acc[0][2 * q2]     = ffma2(r0, w.x, acc[0][2 * q2]);
                    acc[1][2 * q2]     = ffma2(r1, w.x, acc[1][2 * q2]);
                    acc[2][2 * q2]     = ffma2(r2, w.x, acc[2][2 * q2]);
                    acc[3][2 * q2]     = ffma2(r3, w.x, acc[3][2 * q2]);
                    acc[0][2 * q2 + 1] = ffma2(r0, w.y, acc[0][2 * q2 + 1]);
                    acc[1][2 * q2 + 1] = ffma2(r1, w.y, acc[1][2 * q2 + 1]);
                    acc[2][2 * q2 + 1] = ffma2(r2, w.y, acc[2][2 * q2 + 1]);
                    acc[3][2 * q2 + 1] = ffma2(r3, w.y, acc[3][2 * q2 + 1]);
                }
            }
            __syncthreads();   // all reads of sh done before scatter writes sh rows

            // scatter params: padded row r -> st rows 0..63, sh rows 0..15
#pragma unroll
            for (int q = 0; q < 10; ++q) {
                float l0, h0, l1, h1, l2, h2, l3, h3;
                upk2(acc[0][q], l0, h0); upk2(acc[1][q], l1, h1);
                upk2(acc[2][q], l2, h2); upk2(acc[3][q], l3, h3);
                float4 vlo = make_float4(l0, l1, l2, l3);
                float4 vhi = make_float4(h0, h1, h2, h3);
                int r0 = ob + 2 * q, r1 = r0 + 1;
                float* p0 = (r0 < 64 ? st + (r0 << 7) : sh + ((r0 - 64) << 7)) + 4 * tx;
                float* p1 = (r1 < 64 ? st + (r1 << 7) : sh + ((r1 - 64) << 7)) + 4 * tx;
                *reinterpret_cast<float4*>(p0) = vlo;
                *reinterpret_cast<float4*>(p1) = vhi;
            }
        }
        __syncthreads();

        // ---- splines (column = tid) ----
        float y0, l0, y1, l1;
        {
            float p[37];
#pragma unroll
            for (int r = 0; r < 37; ++r) p[r] = st[(r << 7) + tid];
            bool inside = (t0 >= -TBc) && (t0 <= TBc);
            float xc = fminf(fmaxf(t0, -TBc), TBc);
            int bin = 0;
            float in_cw, in_w, in_ch, in_h;
            {
                float e[12]; float m = p[0];
#pragma unroll
                for (int j = 1; j < 12; ++j) m = fmaxf(m, p[j]);
                float s = 0.0f;
#pragma unroll
                for (int j = 0; j < 12; ++j) { e[j] = __expf(p[j] - m); s += e[j]; }
                float ci = 0.988f * __fdividef(1.0f, s);
#pragma unroll
                for (int j = 0; j < 12; ++j) e[j] = fmaf(e[j], ci, MINc);
                float run = 0.0f;
#pragma unroll
                for (int j = 0; j < 12; ++j) {
                    run += e[j];
                    float ks = (j == 11) ? (TBc + 1e-6f) : fmaf(10.0f, run, -TBc);
                    if (xc >= ks) ++bin;
                }
                run = 0.0f; float prev = -TBc;
#pragma unroll
                for (int j = 0; j < 12; ++j) {
                    run += e[j];
                    float right = (j == 11) ? TBc : fmaf(10.0f, run, -TBc);
                    if (j == bin) { in_cw = prev; in_w = right - prev; }
                    prev = right;
                }
            }
            {
                float e[12]; float m = p[12];
#pragma unroll
                for (int j = 1; j < 12; ++j) m = fmaxf(m, p[12 + j]);
                float s = 0.0f;
#pragma unroll
                for (int j = 0; j < 12; ++j) { e[j] = __expf(p[12 + j] - m); s += e[j]; }
                float ci = 0.988f * __fdividef(1.0f, s);
#pragma unroll
                for (int j = 0; j < 12; ++j) e[j] = fmaf(e[j], ci, MINc);
                float run = 0.0f; float prev = -TBc;
#pragma unroll
                for (int j = 0; j < 12; ++j) {
                    run += e[j];
                    float right = (j == 11) ? TBc : fmaf(10.0f, run, -TBc);
                    if (j == bin) { in_ch = prev; in_h = right - prev; }
                    prev = right;
                }
            }
            float uk = DCONSTf, uk1 = DCONSTf;
#pragma unroll
            for (int j = 1; j <= 12; ++j) {
                float v = p[23 + j];
                if (j == bin)     uk  = v;
                if (j == bin + 1) uk1 = v;
            }
            float dk  = MINc + softplusf(uk);
            float dk1 = MINc + softplusf(uk1);
            float invw  = __fdividef(1.0f, in_w);
            float delta = in_h * invw;
            float theta = (xc - in_cw) * invw;
            float om    = 1.0f - theta;
            float t1m   = theta * om;
            float th2   = theta * theta;
            float num   = in_h * (delta * th2 + dk * t1m);
            float den   = delta + (dk + dk1 - 2.0f * delta) * t1m;
            float yv    = in_ch + __fdividef(num, den);
            float dnum  = (delta * delta) * (dk1 * th2 + 2.0f * delta * t1m + dk * om * om);
            float lad   = __logf(dnum) - 2.0f * __logf(den);
            y0 = inside ? yv : t0;
            l0 = inside ? lad : 0.0f;
        }
        {
            float p[37];
#pragma unroll
            for (int r = 40; r < 64; ++r) p[r - 40] = st[(r << 7) + tid];
#pragma unroll
            for (int r = 64; r < 77; ++r) p[r - 40] = sh[((r - 64) << 7) + tid];
            bool inside = (t1 >= -TBc) && (t1 <= TBc);
            float xc = fminf(fmaxf(t1, -TBc), TBc);
            int bin = 0;
            float in_cw, in_w, in_ch, in_h;
            {
                float e[12]; float m = p[0];
#pragma unroll
                for (int j = 1; j < 12; ++j) m = fmaxf(m, p[j]);
                float s = 0.0f;
#pragma unroll
                for (int j = 0; j < 12; ++j) { e[j] = __expf(p[j] - m); s += e[j]; }
                float ci = 0.988f * __fdividef(1.0f, s);
#pragma unroll
                for (int j = 0; j < 12; ++j) e[j] = fmaf(e[j], ci, MINc);
                float run = 0.0f;
#pragma unroll
                for (int j = 0; j < 12; ++j) {
                    run += e[j];
                    float ks = (j == 11) ? (TBc + 1e-6f) : fmaf(10.0f, run, -TBc);
                    if (xc >= ks) ++bin;
                }
                run = 0.0f; float prev = -TBc;
#pragma unroll
                for (int j = 0; j < 12; ++j) {
                    run += e[j];
                    float right = (j == 11) ? TBc : fmaf(10.0f, run, -TBc);
                    if (j == bin) { in_cw = prev; in_w = right - prev; }
                    prev = right;
                }
            }
            {
                float e[12]; float m = p[12];
#pragma unroll
                for (int j = 1; j < 12; ++j) m = fmaxf(m, p[12 + j]);
                float s = 0.0f;
#pragma unroll
                for (int j = 0; j < 12; ++j) { e[j] = __expf(p[12 + j] - m); s += e[j]; }
                float ci = 0.988f * __fdividef(1.0f, s);
#pragma unroll
                for (int j = 0; j < 12; ++j) e[j] = fmaf(e[j], ci, MINc);
                float run = 0.0f; float prev = -TBc;
#pragma unroll
                for (int j = 0; j < 12; ++j) {
                    run += e[j];
                    float right = (j == 11) ? TBc : fmaf(10.0f, run, -TBc);
                    if (j == bin) { in_ch = prev; in_h = right - prev; }
                    prev = right;
                }
            }
            float uk = DCONSTf, uk1 = DCONSTf;
#pragma unroll
            for (int j = 1; j <= 12; ++j) {
                float v = p[23 + j];
                if (j == bin)     uk  = v;
                if (j == bin + 1) uk1 = v;
            }
            float dk  = MINc + softplusf(uk);
            float dk1 = MINc + softplusf(uk1);
            float invw  = __fdividef(1.0f, in_w);
            float delta = in_h * invw;
            float theta = (xc - in_cw) * invw;
            float om    = 1.0f - theta;
            float t1m   = theta * om;
            float th2   = theta * theta;
            float num   = in_h * (delta * th2 + dk * t1m);
            float den   = delta + (dk + dk1 - 2.0f * delta) * t1m;
            float yv    = in_ch + __fdividef(num, den);
            float dnum  = (delta * delta) * (dk1 * th2 + 2.0f * delta * t1m + dk * om * om);
            float lad   = __logf(dnum) - 2.0f * __logf(den);
            y1 = inside ? yv : t1;
            l1 = inside ? lad : 0.0f;
        }

        z0 = c; z1 = y0; z2 = y1;
        lad_total += l0 + l1;
    }

    if (valid)
        out[gidr] = fmaf(-0.5f, z0 * z0 + z1 * z1 + z2 * z2, LOGZc + lad_total);
}

extern "C" void kernel_launch(void* const* d_in, const int* in_sizes, int n_in,
                              void* d_out, int out_size) {
    const float* x     = (const float*)d_in[0];
    const float* W_in  = (const float*)d_in[1];
    const float* b_in  = (const float*)d_in[2];
    const float* W_blk = (const float*)d_in[3];
    const float* b_blk = (const float*)d_in[4];
    const float* W_out = (const float*)d_in[5];
    const float* b_out = (const float*)d_in[6];
    float* out = (float*)d_out;

    int n = in_sizes[0] / 3;
    cudaFuncSetAttribute(nsf_kernel, cudaFuncAttributeMaxDynamicSharedMemorySize,
                         SMEM_BYTES);
    int blocks = (n + COLS - 1) / COLS;
    nsf_kernel<<<blocks, THREADS, SMEM_BYTES>>>(x, W_in, b_in, W_blk, b_blk,
                                                W_out, b_out, out, n);
}

// round 14
// speedup vs baseline: 2.3007x; 2.3007x over previous
#include <cuda_runtime.h>
#include <cuda_bf16.h>
#include <cstdint>

typedef unsigned u32;

#define TBc 5.0f
#define MINc 0.001f
#define LOGZc (-2.7568155996140194f)
#define DCONSTf (0.5397424697f)

// smem byte offsets
#define SM_W   0          // W' panel: 80 rows x 400 B
#define SM_A   32000      // A'/exchange panel: 128 rows x 400 B
#define SM_WIN 83200
#define SM_BIN 83456
#define SM_BB  83712
#define SM_BO  84736
#define SM_CC  85056
#define SM_T1  85568
#define SM_Y1  86080
#define SM_L1  86592
#define SMEM_BYTES 87296

__device__ __nv_bfloat16 g_wh[8 * 4 * 64 * 192];
__device__ __nv_bfloat16 g_wo[8 * 80 * 192];

static __device__ __forceinline__ u32 smem_u32(const void* p) {
    u32 a;
    asm("{ .reg .u64 t; cvta.to.shared.u64 t, %1; cvt.u32.u64 %0, t; }" : "=r"(a) : "l"(p));
    return a;
}
static __device__ __forceinline__ void ldsm4(u32& a0, u32& a1, u32& a2, u32& a3, u32 addr) {
    asm volatile("ldmatrix.sync.aligned.m8n8.x4.shared.b16 {%0,%1,%2,%3}, [%4];"
                 : "=r"(a0), "=r"(a1), "=r"(a2), "=r"(a3) : "r"(addr));
}
static __device__ __forceinline__ void ldsm2(u32& b0, u32& b1, u32 addr) {
    asm volatile("ldmatrix.sync.aligned.m8n8.x2.shared.b16 {%0,%1}, [%2];"
                 : "=r"(b0), "=r"(b1) : "r"(addr));
}
static __device__ __forceinline__ void mma16816(float* d, u32 a0, u32 a1, u32 a2, u32 a3,
                                                u32 b0, u32 b1) {
    asm volatile("mma.sync.aligned.m16n8k16.row.col.f32.bf16.bf16.f32 "
                 "{%0,%1,%2,%3},{%4,%5,%6,%7},{%8,%9},{%0,%1,%2,%3};"
                 : "+f"(d[0]), "+f"(d[1]), "+f"(d[2]), "+f"(d[3])
                 : "r"(a0), "r"(a1), "r"(a2), "r"(a3), "r"(b0), "r"(b1));
}

// ---- converter: W' rows [Whi | Wlo | Whi], linear [rows][192] ----
extern "C" __global__ void conv_kernel(const float* __restrict__ W_blk,
                                       const float* __restrict__ W_out) {
    int idx = blockIdx.x * 256 + threadIdx.x;
    const int T1 = 8 * 4 * 64 * 192;
    if (idx < T1) {
        int kp = idx % 192, nn = (idx / 192) & 63, tl = idx / (192 * 64);
        float wv = W_blk[tl * 4096 + nn * 64 + (kp & 63)];
        __nv_bfloat16 hi = __float2bfloat16(wv);
        g_wh[idx] = (kp >= 64 && kp < 128)
                    ? __float2bfloat16(wv - __bfloat162float(hi)) : hi;
    } else if ((idx -= T1) < 8 * 80 * 192) {
        int kp = idx % 192, r = (idx / 192) % 80, t = idx / (192 * 80);
        int o = (r < 37) ? r : ((r >= 40 && r < 77) ? r - 3 : -1);
        float wv = (o >= 0) ? W_out[(t * 74 + o) * 64 + (kp & 63)] : 0.0f;
        __nv_bfloat16 hi = __float2bfloat16(wv);
        g_wo[idx] = (kp >= 64 && kp < 128)
                    ? __float2bfloat16(wv - __bfloat162float(hi)) : hi;
    }
}

static __device__ __forceinline__ float softplusf(float x) {
    return fmaxf(x, 0.0f) + log1pf(__expf(-fabsf(x)));
}
static __device__ __forceinline__ void rq_spline(const float* __restrict__ p,
                                                 float xin, float& yout, float& ladout) {
    bool inside = (xin >= -TBc) && (xin <= TBc);
    float xc = fminf(fmaxf(xin, -TBc), TBc);
    int bin = 0;
    float in_cw, in_w, in_ch, in_h;
    {
        float e[12]; float m = p[0];
#pragma unroll
        for (int j = 1; j < 12; ++j) m = fmaxf(m, p[j]);
        float s = 0.0f;
#pragma unroll
        for (int j = 0; j < 12; ++j) { e[j] = __expf(p[j] - m); s += e[j]; }
        float ci = 0.988f * __fdividef(1.0f, s);
#pragma unroll
        for (int j = 0; j < 12; ++j) e[j] = fmaf(e[j], ci, MINc);
        float run = 0.0f;
#pragma unroll
        for (int j = 0; j < 12; ++j) {
            run += e[j];
            float ks = (j == 11) ? (TBc + 1e-6f) : fmaf(10.0f, run, -TBc);
            if (xc >= ks) ++bin;
        }
        run = 0.0f; float prev = -TBc;
#pragma unroll
        for (int j = 0; j < 12; ++j) {
            run += e[j];
            float right = (j == 11) ? TBc : fmaf(10.0f, run, -TBc);
            if (j == bin) { in_cw = prev; in_w = right - prev; }
            prev = right;
        }
    }
    {
        float e[12]; float m = p[12];
#pragma unroll
        for (int j = 1; j < 12; ++j) m = fmaxf(m, p[12 + j]);
        float s = 0.0f;
#pragma unroll
        for (int j = 0; j < 12; ++j) { e[j] = __expf(p[12 + j] - m); s += e[j]; }
        float ci = 0.988f * __fdividef(1.0f, s);
#pragma unroll
        for (int j = 0; j < 12; ++j) e[j] = fmaf(e[j], ci, MINc);
        float run = 0.0f; float prev = -TBc;
#pragma unroll
        for (int j = 0; j < 12; ++j) {
            run += e[j];
            float right = (j == 11) ? TBc : fmaf(10.0f, run, -TBc);
            if (j == bin) { in_ch = prev; in_h = right - prev; }
            prev = right;
        }
    }
    float uk = DCONSTf, uk1 = DCONSTf;
#pragma unroll
    for (int j = 1; j <= 12; ++j) {
        float v = p[23 + j];
        if (j == bin)     uk  = v;
        if (j == bin + 1) uk1 = v;
    }
    float dk  = MINc + softplusf(uk);
    float dk1 = MINc + softplusf(uk1);
    float invw  = __fdividef(1.0f, in_w);
    float delta = in_h * invw;
    float theta = (xc - in_cw) * invw;
    float om    = 1.0f - theta;
    float t1m   = theta * om;
    float th2   = theta * theta;
    float num   = in_h * (delta * th2 + dk * t1m);
    float den   = delta + (dk + dk1 - 2.0f * delta) * t1m;
    float yv    = in_ch + __fdividef(num, den);
    float dnum  = (delta * delta) * (dk1 * th2 + 2.0f * delta * t1m + dk * om * om);
    float lad   = __logf(dnum) - 2.0f * __logf(den);
    yout   = inside ? yv : xin;
    ladout = inside ? lad : 0.0f;
}

// stage W' rows into W panel (pitch 400 B)
static __device__ __forceinline__ void stage_w(char* smem, const __nv_bfloat16* src,
                                               int rows, int tid) {
    const uint4* s = (const uint4*)src;
    for (int i = tid; i < rows * 24; i += 256)
        *(uint4*)(smem + SM_W + (i / 24) * 400 + (i % 24) * 16) = s[i];
}

// split frag -> A' panel (hi @o, hi @o+64, lo @o+128), warp-private rows
template<int NT, bool RELU>
static __device__ __forceinline__ void write_act(const float (*f)[4], char* smem,
                                                 int w, int lane) {
    char* base0 = smem + SM_A + (16 * w + (lane >> 2)) * 400;
    char* base1 = base0 + 8 * 400;
    const int ob = (lane & 3) * 2;
#pragma unroll
    for (int j = 0; j < NT; ++j) {
        int o2 = 2 * (8 * j + ob);
        float v0 = f[j][0], v1 = f[j][1], v2 = f[j][2], v3 = f[j][3];
        if (RELU) {
            v0 = fmaxf(v0, 0.0f); v1 = fmaxf(v1, 0.0f);
            v2 = fmaxf(v2, 0.0f); v3 = fmaxf(v3, 0.0f);
        }
        u32 h0, h1, l0, l1;
        asm("cvt.rn.bf16x2.f32 %0, %1, %2;" : "=r"(h0) : "f"(v1), "f"(v0));
        asm("cvt.rn.bf16x2.f32 %0, %1, %2;" : "=r"(h1) : "f"(v3), "f"(v2));
        float e0 = v0 - __uint_as_float(h0 << 16);
        float e1 = v1 - __uint_as_float(h0 & 0xFFFF0000u);
        float e2 = v2 - __uint_as_float(h1 << 16);
        float e3 = v3 - __uint_as_float(h1 & 0xFFFF0000u);
        asm("cvt.rn.bf16x2.f32 %0, %1, %2;" : "=r"(l0) : "f"(e1), "f"(e0));
        asm("cvt.rn.bf16x2.f32 %0, %1, %2;" : "=r"(l1) : "f"(e3), "f"(e2));
        *(u32*)(base0 + o2)       = h0;
        *(u32*)(base0 + o2 + 128) = h0;
        *(u32*)(base0 + o2 + 256) = l0;
        *(u32*)(base1 + o2)       = h1;
        *(u32*)(base1 + o2 + 128) = h1;
        *(u32*)(base1 + o2 + 256) = l1;
    }
}

template<int NT>
static __device__ __forceinline__ void mma_layer(float (*acc)[4], u32 sb, int w, int lane) {
    const int r8 = lane & 7;
    const u32 aAddr = sb + SM_A +
        (u32)((16 * w + r8 + ((lane >> 3) & 1) * 8) * 400 + (lane >> 4) * 16);
    const u32 bAddr = sb + SM_W + (u32)(r8 * 400 + ((lane >> 3) & 1) * 16);
#pragma unroll
    for (int k = 0; k < 12; ++k) {
        u32 a0, a1, a2, a3;
        ldsm4(a0, a1, a2, a3, aAddr + k * 32);
#pragma unroll
        for (int j = 0; j < NT; ++j) {
            u32 b0, b1;
            ldsm2(b0, b1, bAddr + j * 3200 + k * 32);
            mma16816(acc[j], a0, a1, a2, a3, b0, b1);
        }
    }
}

template<int NT>
static __device__ __forceinline__ void add_bias(float (*acc)[4], const float* b, int lane) {
    const int ob = (lane & 3) * 2;
#pragma unroll
    for (int j = 0; j < NT; ++j) {
        float2 bb = *(const float2*)(b + 8 * j + ob);
        acc[j][0] += bb.x; acc[j][1] += bb.y;
        acc[j][2] += bb.x; acc[j][3] += bb.y;
    }
}

extern "C" __global__ void __launch_bounds__(256)
nsf_tc(const float* __restrict__ x,
       const float* __restrict__ W_in, const float* __restrict__ b_in,
       const float* __restrict__ b_blk, const float* __restrict__ b_out,
       float* __restrict__ out, int n) {
    extern __shared__ char smem[];
    const u32 sb = smem_u32(smem);
    float* sWIN = (float*)(smem + SM_WIN);
    float* sBIN = (float*)(smem + SM_BIN);
    float* sBB  = (float*)(smem + SM_BB);
    float* sBO  = (float*)(smem + SM_BO);
    float* sCC  = (float*)(smem + SM_CC);
    float* sT1  = (float*)(smem + SM_T1);
    float* sY1  = (float*)(smem + SM_Y1);
    float* sL1  = (float*)(smem + SM_L1);

    const int tid = threadIdx.x, lane = tid & 31, w = tid >> 5;
    const bool grpA = tid < 128;
    const int gidr = blockIdx.x * 128 + tid;
    const bool valid = grpA && (gidr < n);
    const int g = valid ? gidr : (n - 1);

    float z0 = 0.0f, z1 = 0.0f, z2 = 0.0f, lad = 0.0f;
    if (grpA) { z0 = x[3 * g]; z1 = x[3 * g + 1]; z2 = x[3 * g + 2]; }

    for (int it = 0; it < 8; ++it) {
        __syncthreads();
        if (tid < 64) { sWIN[tid] = W_in[it * 64 + tid]; sBIN[tid] = b_in[it * 64 + tid]; }
        sBB[tid] = b_blk[it * 256 + tid];
        if (tid < 80) {
            float v = 0.0f;
            if (tid < 37) v = b_out[it * 74 + tid];
            else if (tid >= 40 && tid < 77) v = b_out[it * 74 + tid - 3];
            sBO[tid] = v;
        }
        float c = 0.0f, t0 = 0.0f;
        if (grpA) { c = z2; t0 = z1; sCC[tid] = c; sT1[tid] = z0; }
        stage_w(smem, g_wh + (it * 4 + 0) * 12288, 64, tid);
        __syncthreads();

        // h-init fragments
        float hA[8][4], tA[10][4];
        {
            int r0 = 16 * w + (lane >> 2);
            float c0 = sCC[r0], c1 = sCC[r0 + 8];
            const int ob = (lane & 3) * 2;
#pragma unroll
            for (int j = 0; j < 8; ++j) {
                int o = 8 * j + ob;
                float2 wi = *(const float2*)(sWIN + o);
                float2 bi = *(const float2*)(sBIN + o);
                hA[j][0] = fmaf(c0, wi.x, bi.x); hA[j][1] = fmaf(c0, wi.y, bi.y);
                hA[j][2] = fmaf(c1, wi.x, bi.x); hA[j][3] = fmaf(c1, wi.y, bi.y);
            }
        }
        // L1
        write_act<8, true>(hA, smem, w, lane);
        __syncwarp();
#pragma unroll
        for (int j = 0; j < 8; ++j) { tA[j][0] = tA[j][1] = tA[j][2] = tA[j][3] = 0.0f; }
        mma_layer<8>(tA, sb, w, lane);
        add_bias<8>(tA, sBB, lane);
        __syncthreads();
        stage_w(smem, g_wh + (it * 4 + 1) * 12288, 64, tid);
        __syncthreads();
        // L2 (acc = h)
        write_act<8, true>(tA, smem, w, lane);
        __syncwarp();
        mma_layer<8>(hA, sb, w, lane);
        add_bias<8>(hA, sBB + 64, lane);
        __syncthreads();
        stage_w(smem, g_wh + (it * 4 + 2) * 12288, 64, tid);
        __syncthreads();
        // L3
        write_act<8, true>(hA, smem, w, lane);
        __syncwarp();
#pragma unroll
        for (int j = 0; j < 8; ++j) { tA[j][0] = tA[j][1] = tA[j][2] = tA[j][3] = 0.0f; }
        mma_layer<8>(tA, sb, w, lane);
        add_bias<8>(tA, sBB + 128, lane);
        __syncthreads();
        stage_w(smem, g_wh + (it * 4 + 3) * 12288, 64, tid);
        __syncthreads();
        // L4 (acc = h)
        write_act<8, true>(tA, smem, w, lane);
        __syncwarp();
        mma_layer<8>(hA, sb, w, lane);
        add_bias<8>(hA, sBB + 192, lane);
        __syncthreads();
        stage_w(smem, g_wo + it * 15360, 80, tid);
        __syncthreads();
        // Out (N=80, no relu on input)
        write_act<8, false>(hA, smem, w, lane);
        __syncwarp();
#pragma unroll
        for (int j = 0; j < 10; ++j) { tA[j][0] = tA[j][1] = tA[j][2] = tA[j][3] = 0.0f; }
        mma_layer<10>(tA, sb, w, lane);
        add_bias<10>(tA, sBO, lane);
        // exchange params (fp32) into A-panel rows
        {
            char* e0 = smem + SM_A + (16 * w + (lane >> 2)) * 400;
            char* e1 = e0 + 3200;
            const int ob = (lane & 3) * 2;
#pragma unroll
            for (int j = 0; j < 10; ++j) {
                int o4 = 4 * (8 * j + ob);
                *(float2*)(e0 + o4) = make_float2(tA[j][0], tA[j][1]);
                *(float2*)(e1 + o4) = make_float2(tA[j][2], tA[j][3]);
            }
        }
        __syncthreads();

        // splines: grpA dim0 (cols 0..36), grpB dim1 (cols 40..76)
        float y0 = 0.0f, l0v = 0.0f;
        if (grpA) {
            const char* row = smem + SM_A + tid * 400;
            float p[37];
#pragma unroll
            for (int r = 0; r < 37; ++r) p[r] = *(const float*)(row + 4 * r);
            rq_spline(p, t0, y0, l0v);
        } else {
            int pt = tid - 128;
            const char* row = smem + SM_A + pt * 400;
            float p[37];
#pragma unroll
            for (int r = 0; r < 37; ++r) p[r] = *(const float*)(row + 4 * (40 + r));
            float yb, lb;
            rq_spline(p, sT1[pt], yb, lb);
            sY1[pt] = yb; sL1[pt] = lb;
        }
        __syncthreads();
        if (grpA) {
            z0 = c; z1 = y0; z2 = sY1[tid];
            lad += l0v + sL1[tid];
        }
    }

    if (valid)
        out[gidr] = fmaf(-0.5f, z0 * z0 + z1 * z1 + z2 * z2, LOGZc + lad);
}

extern "C" void kernel_launch(void* const* d_in, const int* in_sizes, int n_in,
                              void* d_out, int out_size) {
    const float* x     = (const float*)d_in[0];
    const float* W_in  = (const float*)d_in[1];
    const float* b_in  = (const float*)d_in[2];
    const float* W_blk = (const float*)d_in[3];
    const float* b_blk = (const float*)d_in[4];
    const float* W_out = (const float*)d_in[5];
    const float* b_out = (const float*)d_in[6];
    float* out = (float*)d_out;

    int n = in_sizes[0] / 3;
    conv_kernel<<<(8 * 4 * 64 * 192 + 8 * 80 * 192 + 255) / 256, 256>>>(W_blk, W_out);
    cudaFuncSetAttribute(nsf_tc, cudaFuncAttributeMaxDynamicSharedMemorySize, SMEM_BYTES);
    nsf_tc<<<(n + 127) / 128, 256, SMEM_BYTES>>>(x, W_in, b_in, b_blk, b_out, out, n);
}

// round 16
// speedup vs baseline: 2.7011x; 1.1741x over previous
#include <cuda_runtime.h>
#include <cuda_bf16.h>
#include <cstdint>

typedef unsigned u32;

#define TBc 5.0f
#define MINc 0.001f
#define LOGZc (-2.7568155996140194f)
#define DCONSTf (0.5397424697f)

// smem byte offsets
#define SM_W   0          // W' panel: 80 rows x 400 B
#define SM_A   32000      // A' panel: 128 rows x 400 B (also exchange @ 396 pitch)
#define SM_WIN 83200
#define SM_BIN 83456
#define SM_BB  83712
#define SM_BO  84736
#define SM_CC  85056
#define SMEM_BYTES 85568   // 2 CTAs/SM

__device__ __nv_bfloat16 g_wh[8 * 4 * 64 * 192];
__device__ __nv_bfloat16 g_wo[8 * 80 * 192];

static __device__ __forceinline__ u32 smem_u32(const void* p) {
    u32 a;
    asm("{ .reg .u64 t; cvta.to.shared.u64 t, %1; cvt.u32.u64 %0, t; }" : "=r"(a) : "l"(p));
    return a;
}
static __device__ __forceinline__ void ldsm4(u32& a0, u32& a1, u32& a2, u32& a3, u32 addr) {
    asm volatile("ldmatrix.sync.aligned.m8n8.x4.shared.b16 {%0,%1,%2,%3}, [%4];"
                 : "=r"(a0), "=r"(a1), "=r"(a2), "=r"(a3) : "r"(addr));
}
static __device__ __forceinline__ void mma16816(float* d, u32 a0, u32 a1, u32 a2, u32 a3,
                                                u32 b0, u32 b1) {
    asm volatile("mma.sync.aligned.m16n8k16.row.col.f32.bf16.bf16.f32 "
                 "{%0,%1,%2,%3},{%4,%5,%6,%7},{%8,%9},{%0,%1,%2,%3};"
                 : "+f"(d[0]), "+f"(d[1]), "+f"(d[2]), "+f"(d[3])
                 : "r"(a0), "r"(a1), "r"(a2), "r"(a3), "r"(b0), "r"(b1));
}

// ---- converter: W' rows [Whi | Wlo | Whi], linear [rows][192] ----
extern "C" __global__ void conv_kernel(const float* __restrict__ W_blk,
                                       const float* __restrict__ W_out) {
    int idx = blockIdx.x * 256 + threadIdx.x;
    const int T1 = 8 * 4 * 64 * 192;
    if (idx < T1) {
        int kp = idx % 192, nn = (idx / 192) & 63, tl = idx / (192 * 64);
        float wv = W_blk[tl * 4096 + nn * 64 + (kp & 63)];
        __nv_bfloat16 hi = __float2bfloat16(wv);
        g_wh[idx] = (kp >= 64 && kp < 128)
                    ? __float2bfloat16(wv - __bfloat162float(hi)) : hi;
    } else if ((idx -= T1) < 8 * 80 * 192) {
        int kp = idx % 192, r = (idx / 192) % 80, t = idx / (192 * 80);
        int o = (r < 37) ? r : ((r >= 40 && r < 77) ? r - 3 : -1);
        float wv = (o >= 0) ? W_out[(t * 74 + o) * 64 + (kp & 63)] : 0.0f;
        __nv_bfloat16 hi = __float2bfloat16(wv);
        g_wo[idx] = (kp >= 64 && kp < 128)
                    ? __float2bfloat16(wv - __bfloat162float(hi)) : hi;
    }
}

static __device__ __forceinline__ float softplusf(float x) {
    return fmaxf(x, 0.0f) + log1pf(__expf(-fabsf(x)));
}
static __device__ __forceinline__ void rq_spline(const float* __restrict__ p,
                                                 float xin, float& yout, float& ladout) {
    bool inside = (xin >= -TBc) && (xin <= TBc);
    float xc = fminf(fmaxf(xin, -TBc), TBc);
    int bin = 0;
    float in_cw, in_w, in_ch, in_h;
    {
        float e[12]; float m = p[0];
#pragma unroll
        for (int j = 1; j < 12; ++j) m = fmaxf(m, p[j]);
        float s = 0.0f;
#pragma unroll
        for (int j = 0; j < 12; ++j) { e[j] = __expf(p[j] - m); s += e[j]; }
        float ci = 0.988f * __fdividef(1.0f, s);
#pragma unroll
        for (int j = 0; j < 12; ++j) e[j] = fmaf(e[j], ci, MINc);
        float run = 0.0f;
#pragma unroll
        for (int j = 0; j < 12; ++j) {
            run += e[j];
            float ks = (j == 11) ? (TBc + 1e-6f) : fmaf(10.0f, run, -TBc);
            if (xc >= ks) ++bin;
        }
        run = 0.0f; float prev = -TBc;
#pragma unroll
        for (int j = 0; j < 12; ++j) {
            run += e[j];
            float right = (j == 11) ? TBc : fmaf(10.0f, run, -TBc);
            if (j == bin) { in_cw = prev; in_w = right - prev; }
            prev = right;
        }
    }
    {
        float e[12]; float m = p[12];
#pragma unroll
        for (int j = 1; j < 12; ++j) m = fmaxf(m, p[12 + j]);
        float s = 0.0f;
#pragma unroll
        for (int j = 0; j < 12; ++j) { e[j] = __expf(p[12 + j] - m); s += e[j]; }
        float ci = 0.988f * __fdividef(1.0f, s);
#pragma unroll
        for (int j = 0; j < 12; ++j) e[j] = fmaf(e[j], ci, MINc);
        float run = 0.0f; float prev = -TBc;
#pragma unroll
        for (int j = 0; j < 12; ++j) {
            run += e[j];
            float right = (j == 11) ? TBc : fmaf(10.0f, run, -TBc);
            if (j == bin) { in_ch = prev; in_h = right - prev; }
            prev = right;
        }
    }
    float uk = DCONSTf, uk1 = DCONSTf;
#pragma unroll
    for (int j = 1; j <= 12; ++j) {
        float v = p[23 + j];
        if (j == bin)     uk  = v;
        if (j == bin + 1) uk1 = v;
    }
    float dk  = MINc + softplusf(uk);
    float dk1 = MINc + softplusf(uk1);
    float invw  = __fdividef(1.0f, in_w);
    float delta = in_h * invw;
    float theta = (xc - in_cw) * invw;
    float om    = 1.0f - theta;
    float t1m   = theta * om;
    float th2   = theta * theta;
    float num   = in_h * (delta * th2 + dk * t1m);
    float den   = delta + (dk + dk1 - 2.0f * delta) * t1m;
    float yv    = in_ch + __fdividef(num, den);
    float dnum  = (delta * delta) * (dk1 * th2 + 2.0f * delta * t1m + dk * om * om);
    float lad   = __logf(dnum) - 2.0f * __logf(den);
    yout   = inside ? yv : xin;
    ladout = inside ? lad : 0.0f;
}

// stage W' rows into W panel (pitch 400 B), 128 threads
static __device__ __forceinline__ void stage_w(char* smem, const __nv_bfloat16* src,
                                               int rows, int tid) {
    const uint4* s = (const uint4*)src;
    for (int i = tid; i < rows * 24; i += 128)
        *(uint4*)(smem + SM_W + (i / 24) * 400 + (i % 24) * 16) = s[i];
}

// split two M-tiles of fragments -> A' panel [hi | hi | lo]; warp-private rows
template<int NT, bool RELU>
static __device__ __forceinline__ void write_act2(const float (*f0)[4], const float (*f1)[4],
                                                  char* smem, int w, int lane) {
    const int r0 = 32 * w + (lane >> 2);
    const int ob = (lane & 3) * 2;
    char* b0 = smem + SM_A + r0 * 400;
#pragma unroll
    for (int t = 0; t < 4; ++t) {          // 4 row-groups: r0, r0+8, r0+16, r0+24
        char* base = b0 + t * 8 * 400;
#pragma unroll
        for (int j = 0; j < NT; ++j) {
            const float* f = (t < 2) ? f0[j] : f1[j];
            float v0 = f[(t & 1) * 2], v1 = f[(t & 1) * 2 + 1];
            if (RELU) { v0 = fmaxf(v0, 0.0f); v1 = fmaxf(v1, 0.0f); }
            u32 h, l;
            asm("cvt.rn.bf16x2.f32 %0, %1, %2;" : "=r"(h) : "f"(v1), "f"(v0));
            float e0 = v0 - __uint_as_float(h << 16);
            float e1 = v1 - __uint_as_float(h & 0xFFFF0000u);
            asm("cvt.rn.bf16x2.f32 %0, %1, %2;" : "=r"(l) : "f"(e1), "f"(e0));
            int o2 = 2 * (8 * j + ob);
            *(u32*)(base + o2)       = h;
            *(u32*)(base + o2 + 128) = h;
            *(u32*)(base + o2 + 256) = l;
        }
    }
}

// two M-tiles x NT n-tiles; B loaded once per pair via ldsm4
template<int NT>
static __device__ __forceinline__ void mma_layer2(float (*acc0)[4], float (*acc1)[4],
                                                  u32 sb, int w, int lane) {
    const u32 aAddr0 = sb + SM_A +
        (u32)((32 * w + (lane & 7) + ((lane >> 3) & 1) * 8) * 400 + (lane >> 4) * 16);
    const u32 aAddr1 = aAddr0 + 16 * 400;
    const u32 bAddr = sb + SM_W +
        (u32)(((lane & 7) + ((lane >> 4) << 3)) * 400 + ((lane >> 3) & 1) * 16);
#pragma unroll
    for (int k = 0; k < 12; ++k) {
        u32 a0, a1, a2, a3, c0, c1, c2, c3;
        ldsm4(a0, a1, a2, a3, aAddr0 + k * 32);
        ldsm4(c0, c1, c2, c3, aAddr1 + k * 32);
#pragma unroll
        for (int jp = 0; jp < NT / 2; ++jp) {
            u32 b0, b1, b2, b3;
            ldsm4(b0, b1, b2, b3, bAddr + jp * 6400 + k * 32);
            mma16816(acc0[2 * jp],     a0, a1, a2, a3, b0, b1);
            mma16816(acc0[2 * jp + 1], a0, a1, a2, a3, b2, b3);
            mma16816(acc1[2 * jp],     c0, c1, c2, c3, b0, b1);
            mma16816(acc1[2 * jp + 1], c0, c1, c2, c3, b2, b3);
        }
    }
}

template<int NT>
static __device__ __forceinline__ void add_bias2(float (*a0)[4], float (*a1)[4],
                                                 const float* b, int lane) {
    const int ob = (lane & 3) * 2;
#pragma unroll
    for (int j = 0; j < NT; ++j) {
        float2 bb = *(const float2*)(b + 8 * j + ob);
        a0[j][0] += bb.x; a0[j][1] += bb.y; a0[j][2] += bb.x; a0[j][3] += bb.y;
        a1[j][0] += bb.x; a1[j][1] += bb.y; a1[j][2] += bb.x; a1[j][3] += bb.y;
    }
}
template<int NT>
static __device__ __forceinline__ void zero2(float (*a0)[4], float (*a1)[4]) {
#pragma unroll
    for (int j = 0; j < NT; ++j) {
        a0[j][0] = a0[j][1] = a0[j][2] = a0[j][3] = 0.0f;
        a1[j][0] = a1[j][1] = a1[j][2] = a1[j][3] = 0.0f;
    }
}

extern "C" __global__ void __launch_bounds__(128)
nsf_tc(const float* __restrict__ x,
       const float* __restrict__ W_in, const float* __restrict__ b_in,
       const float* __restrict__ b_blk, const float* __restrict__ b_out,
       float* __restrict__ out, int n) {
    extern __shared__ char smem[];
    const u32 sb = smem_u32(smem);
    float* sWIN = (float*)(smem + SM_WIN);
    float* sBIN = (float*)(smem + SM_BIN);
    float* sBB  = (float*)(smem + SM_BB);
    float* sBO  = (float*)(smem + SM_BO);
    float* sCC  = (float*)(smem + SM_CC);

    const int tid = threadIdx.x, lane = tid & 31, w = tid >> 5;
    const int gidr = blockIdx.x * 128 + tid;
    const bool valid = gidr < n;
    const int g = valid ? gidr : (n - 1);

    float z0 = x[3 * g], z1 = x[3 * g + 1], z2 = x[3 * g + 2];
    float lad = 0.0f;

    for (int it = 0; it < 8; ++it) {
        __syncthreads();
        if (tid < 64) { sWIN[tid] = W_in[it * 64 + tid]; sBIN[tid] = b_in[it * 64 + tid]; }
        for (int i = tid; i < 256; i += 128) sBB[i] = b_blk[it * 256 + i];
        if (tid < 80) {
            float v = 0.0f;
            if (tid < 37) v = b_out[it * 74 + tid];
            else if (tid >= 40 && tid < 77) v = b_out[it * 74 + tid - 3];
            sBO[tid] = v;
        }
        float c = z2, t0 = z1, t1 = z0;    // reversed z
        sCC[tid] = c;
        stage_w(smem, g_wh + (it * 4 + 0) * 12288, 64, tid);
        __syncthreads();

        // h-init fragments for both M-tiles
        float hA0[8][4], hA1[8][4], tA0[10][4], tA1[10][4];
        {
            int r0 = 32 * w + (lane >> 2);
            float c00 = sCC[r0], c01 = sCC[r0 + 8];
            float c10 = sCC[r0 + 16], c11 = sCC[r0 + 24];
            const int ob = (lane & 3) * 2;
#pragma unroll
            for (int j = 0; j < 8; ++j) {
                int o = 8 * j + ob;
                float2 wi = *(const float2*)(sWIN + o);
                float2 bi = *(const float2*)(sBIN + o);
                hA0[j][0] = fmaf(c00, wi.x, bi.x); hA0[j][1] = fmaf(c00, wi.y, bi.y);
                hA0[j][2] = fmaf(c01, wi.x, bi.x); hA0[j][3] = fmaf(c01, wi.y, bi.y);
                hA1[j][0] = fmaf(c10, wi.x, bi.x); hA1[j][1] = fmaf(c10, wi.y, bi.y);
                hA1[j][2] = fmaf(c11, wi.x, bi.x); hA1[j][3] = fmaf(c11, wi.y, bi.y);
            }
        }
        // L1
        write_act2<8, true>(hA0, hA1, smem, w, lane);
        __syncwarp();
        zero2<8>(tA0, tA1);
        mma_layer2<8>(tA0, tA1, sb, w, lane);
        add_bias2<8>(tA0, tA1, sBB, lane);
        // L2 (acc = h)
        write_act2<8, true>(tA0, tA1, smem, w, lane);
        __syncthreads();
        stage_w(smem, g_wh + (it * 4 + 1) * 12288, 64, tid);
        __syncthreads();
        mma_layer2<8>(hA0, hA1, sb, w, lane);
        add_bias2<8>(hA0, hA1, sBB + 64, lane);
        // L3
        write_act2<8, true>(hA0, hA1, smem, w, lane);
        __syncthreads();
        stage_w(smem, g_wh + (it * 4 + 2) * 12288, 64, tid);
        __syncthreads();
        zero2<8>(tA0, tA1);
        mma_layer2<8>(tA0, tA1, sb, w, lane);
        add_bias2<8>(tA0, tA1, sBB + 128, lane);
        // L4 (acc = h)
        write_act2<8, true>(tA0, tA1, smem, w, lane);
        __syncthreads();
        stage_w(smem, g_wh + (it * 4 + 3) * 12288, 64, tid);
        __syncthreads();
        mma_layer2<8>(hA0, hA1, sb, w, lane);
        add_bias2<8>(hA0, hA1, sBB + 192, lane);
        // Out (N=80, no relu on input)
        write_act2<8, false>(hA0, hA1, smem, w, lane);
        __syncthreads();
        stage_w(smem, g_wo + it * 15360, 80, tid);
        __syncthreads();
        zero2<10>(tA0, tA1);
        mma_layer2<10>(tA0, tA1, sb, w, lane);
        add_bias2<10>(tA0, tA1, sBO, lane);
        __syncthreads();   // all mma reads of A panel done before exchange overwrite

        // exchange params fp32 into A region at 396-B pitch (conflict-free gather).
        // NOTE: scalar 4-byte stores — 396 is only 4-byte aligned for odd rows.
        {
            const int r0 = 32 * w + (lane >> 2);
            const int ob = (lane & 3) * 2;
#pragma unroll
            for (int t = 0; t < 4; ++t) {
                char* e = smem + SM_A + (r0 + t * 8) * 396;
#pragma unroll
                for (int j = 0; j < 10; ++j) {
                    const float* f = (t < 2) ? tA0[j] : tA1[j];
                    int o4 = 4 * (8 * j + ob);
                    *(float*)(e + o4)     = f[(t & 1) * 2];
                    *(float*)(e + o4 + 4) = f[(t & 1) * 2 + 1];
                }
            }
        }
        __syncthreads();

        // splines: thread = point, both dims
        const char* row = smem + SM_A + tid * 396;
        float y0, l0v, y1, l1v;
        {
            float p[37];
#pragma unroll
            for (int r = 0; r < 37; ++r) p[r] = *(const float*)(row + 4 * r);
            rq_spline(p, t0, y0, l0v);
        }
        {
            float p[37];
#pragma unroll
            for (int r = 0; r < 37; ++r) p[r] = *(const float*)(row + 4 * (40 + r));
            rq_spline(p, t1, y1, l1v);
        }
        z0 = c; z1 = y0; z2 = y1;
        lad += l0v + l1v;
    }

    if (valid)
        out[gidr] = fmaf(-0.5f, z0 * z0 + z1 * z1 + z2 * z2, LOGZc + lad);
}

extern "C" void kernel_launch(void* const* d_in, const int* in_sizes, int n_in,
                              void* d_out, int out_size) {
    const float* x     = (const float*)d_in[0];
    const float* W_in  = (const float*)d_in[1];
    const float* b_in  = (const float*)d_in[2];
    const float* W_blk = (const float*)d_in[3];
    const float* b_blk = (const float*)d_in[4];
    const float* W_out = (const float*)d_in[5];
    const float* b_out = (const float*)d_in[6];
    float* out = (float*)d_out;

    int n = in_sizes[0] / 3;
    conv_kernel<<<(8 * 4 * 64 * 192 + 8 * 80 * 192 + 255) / 256, 256>>>(W_blk, W_out);
    cudaFuncSetAttribute(nsf_tc, cudaFuncAttributeMaxDynamicSharedMemorySize, SMEM_BYTES);
    nsf_tc<<<(n + 127) / 128, 128, SMEM_BYTES>>>(x, W_in, b_in, b_blk, b_out, out, n);
}

// round 17
// speedup vs baseline: 3.0208x; 1.1184x over previous
#include <cuda_runtime.h>
#include <cuda_bf16.h>
#include <cstdint>

typedef unsigned u32;

#define TBc 5.0f
#define MINc 0.001f
#define LOGZc (-2.7568155996140194f)
#define DCONSTf (0.5397424697f)

// smem byte offsets
#define SM_W   0          // W' panel: 80 rows x 400 B (192 bf16 cols)
#define SM_A   32000      // A' panel: 128 rows x 272 B ([hi(64)|lo(64)] bf16)
#define SM_WIN 66816
#define SM_BIN 67072
#define SM_BB  67328
#define SM_BO  68352
#define SM_CC  68672
#define SMEM_BYTES 69248   // 3 CTAs/SM

__device__ __nv_bfloat16 g_wh[8 * 4 * 64 * 192];
__device__ __nv_bfloat16 g_wo[8 * 80 * 192];

static __device__ __forceinline__ u32 smem_u32(const void* p) {
    u32 a;
    asm("{ .reg .u64 t; cvta.to.shared.u64 t, %1; cvt.u32.u64 %0, t; }" : "=r"(a) : "l"(p));
    return a;
}
static __device__ __forceinline__ void ldsm4(u32& a0, u32& a1, u32& a2, u32& a3, u32 addr) {
    asm volatile("ldmatrix.sync.aligned.m8n8.x4.shared.b16 {%0,%1,%2,%3}, [%4];"
                 : "=r"(a0), "=r"(a1), "=r"(a2), "=r"(a3) : "r"(addr));
}
static __device__ __forceinline__ void mma16816(float* d, const u32* a, u32 b0, u32 b1) {
    asm volatile("mma.sync.aligned.m16n8k16.row.col.f32.bf16.bf16.f32 "
                 "{%0,%1,%2,%3},{%4,%5,%6,%7},{%8,%9},{%0,%1,%2,%3};"
                 : "+f"(d[0]), "+f"(d[1]), "+f"(d[2]), "+f"(d[3])
                 : "r"(a[0]), "r"(a[1]), "r"(a[2]), "r"(a[3]), "r"(b0), "r"(b1));
}

// ---- converter: W' rows [Whi | Wlo | Whi], linear [rows][192] ----
extern "C" __global__ void conv_kernel(const float* __restrict__ W_blk,
                                       const float* __restrict__ W_out) {
    int idx = blockIdx.x * 256 + threadIdx.x;
    const int T1 = 8 * 4 * 64 * 192;
    if (idx < T1) {
        int kp = idx % 192, nn = (idx / 192) & 63, tl = idx / (192 * 64);
        float wv = W_blk[tl * 4096 + nn * 64 + (kp & 63)];
        __nv_bfloat16 hi = __float2bfloat16(wv);
        g_wh[idx] = (kp >= 64 && kp < 128)
                    ? __float2bfloat16(wv - __bfloat162float(hi)) : hi;
    } else if ((idx -= T1) < 8 * 80 * 192) {
        int kp = idx % 192, r = (idx / 192) % 80, t = idx / (192 * 80);
        int o = (r < 37) ? r : ((r >= 40 && r < 77) ? r - 3 : -1);
        float wv = (o >= 0) ? W_out[(t * 74 + o) * 64 + (kp & 63)] : 0.0f;
        __nv_bfloat16 hi = __float2bfloat16(wv);
        g_wo[idx] = (kp >= 64 && kp < 128)
                    ? __float2bfloat16(wv - __bfloat162float(hi)) : hi;
    }
}

static __device__ __forceinline__ float softplusf(float x) {
    return fmaxf(x, 0.0f) + log1pf(__expf(-fabsf(x)));
}
static __device__ __forceinline__ void rq_spline(const float* __restrict__ p,
                                                 float xin, float& yout, float& ladout) {
    bool inside = (xin >= -TBc) && (xin <= TBc);
    float xc = fminf(fmaxf(xin, -TBc), TBc);
    int bin = 0;
    float in_cw, in_w, in_ch, in_h;
    {
        float e[12]; float m = p[0];
#pragma unroll
        for (int j = 1; j < 12; ++j) m = fmaxf(m, p[j]);
        float s = 0.0f;
#pragma unroll
        for (int j = 0; j < 12; ++j) { e[j] = __expf(p[j] - m); s += e[j]; }
        float ci = 0.988f * __fdividef(1.0f, s);
#pragma unroll
        for (int j = 0; j < 12; ++j) e[j] = fmaf(e[j], ci, MINc);
        float run = 0.0f;
#pragma unroll
        for (int j = 0; j < 12; ++j) {
            run += e[j];
            float ks = (j == 11) ? (TBc + 1e-6f) : fmaf(10.0f, run, -TBc);
            if (xc >= ks) ++bin;
        }
        run = 0.0f; float prev = -TBc;
#pragma unroll
        for (int j = 0; j < 12; ++j) {
            run += e[j];
            float right = (j == 11) ? TBc : fmaf(10.0f, run, -TBc);
            if (j == bin) { in_cw = prev; in_w = right - prev; }
            prev = right;
        }
    }
    {
        float e[12]; float m = p[12];
#pragma unroll
        for (int j = 1; j < 12; ++j) m = fmaxf(m, p[12 + j]);
        float s = 0.0f;
#pragma unroll
        for (int j = 0; j < 12; ++j) { e[j] = __expf(p[12 + j] - m); s += e[j]; }
        float ci = 0.988f * __fdividef(1.0f, s);
#pragma unroll
        for (int j = 0; j < 12; ++j) e[j] = fmaf(e[j], ci, MINc);
        float run = 0.0f; float prev = -TBc;
#pragma unroll
        for (int j = 0; j < 12; ++j) {
            run += e[j];
            float right = (j == 11) ? TBc : fmaf(10.0f, run, -TBc);
            if (j == bin) { in_ch = prev; in_h = right - prev; }
            prev = right;
        }
    }
    float uk = DCONSTf, uk1 = DCONSTf;
#pragma unroll
    for (int j = 1; j <= 12; ++j) {
        float v = p[23 + j];
        if (j == bin)     uk  = v;
        if (j == bin + 1) uk1 = v;
    }
    float dk  = MINc + softplusf(uk);
    float dk1 = MINc + softplusf(uk1);
    float invw  = __fdividef(1.0f, in_w);
    float delta = in_h * invw;
    float theta = (xc - in_cw) * invw;
    float om    = 1.0f - theta;
    float t1m   = theta * om;
    float th2   = theta * theta;
    float num   = in_h * (delta * th2 + dk * t1m);
    float den   = delta + (dk + dk1 - 2.0f * delta) * t1m;
    float yv    = in_ch + __fdividef(num, den);
    float dnum  = (delta * delta) * (dk1 * th2 + 2.0f * delta * t1m + dk * om * om);
    float lad   = __logf(dnum) - 2.0f * __logf(den);
    yout   = inside ? yv : xin;
    ladout = inside ? lad : 0.0f;
}

// stage W' rows into W panel (pitch 400 B), 128 threads
static __device__ __forceinline__ void stage_w(char* smem, const __nv_bfloat16* src,
                                               int rows, int tid) {
    const uint4* s = (const uint4*)src;
    for (int i = tid; i < rows * 24; i += 128)
        *(uint4*)(smem + SM_W + (i / 24) * 400 + (i % 24) * 16) = s[i];
}

// split two M-tiles of fragments -> A' panel [hi | lo], pitch 272
template<int NT, bool RELU>
static __device__ __forceinline__ void write_act2(const float (*f0)[4], const float (*f1)[4],
                                                  char* smem, int w, int lane) {
    const int r0 = 32 * w + (lane >> 2);
    const int ob = (lane & 3) * 2;
    char* b0 = smem + SM_A + r0 * 272;
#pragma unroll
    for (int t = 0; t < 4; ++t) {
        char* base = b0 + t * 8 * 272;
#pragma unroll
        for (int j = 0; j < NT; ++j) {
            const float* f = (t < 2) ? f0[j] : f1[j];
            float v0 = f[(t & 1) * 2], v1 = f[(t & 1) * 2 + 1];
            if (RELU) { v0 = fmaxf(v0, 0.0f); v1 = fmaxf(v1, 0.0f); }
            u32 h, l;
            asm("cvt.rn.bf16x2.f32 %0, %1, %2;" : "=r"(h) : "f"(v1), "f"(v0));
            float e0 = v0 - __uint_as_float(h << 16);
            float e1 = v1 - __uint_as_float(h & 0xFFFF0000u);
            asm("cvt.rn.bf16x2.f32 %0, %1, %2;" : "=r"(l) : "f"(e1), "f"(e0));
            int o2 = 2 * (8 * j + ob);
            *(u32*)(base + o2)       = h;
            *(u32*)(base + o2 + 128) = l;
        }
    }
}

// two M-tiles x NT n-tiles; A-hi fragments cached across chunks 0-7
template<int NT>
static __device__ __forceinline__ void mma_layer2(float (*acc0)[4], float (*acc1)[4],
                                                  u32 sb, int w, int lane) {
    const u32 aAddr0 = sb + SM_A +
        (u32)((32 * w + (lane & 7) + ((lane >> 3) & 1) * 8) * 272 + (lane >> 4) * 16);
    const u32 aAddr1 = aAddr0 + 16 * 272;
    const u32 bAddr = sb + SM_W +
        (u32)(((lane & 7) + ((lane >> 4) << 3)) * 400 + ((lane >> 3) & 1) * 16);
    u32 ah0[4][4], ah1[4][4];
#pragma unroll
    for (int q = 0; q < 4; ++q) {
        ldsm4(ah0[q][0], ah0[q][1], ah0[q][2], ah0[q][3], aAddr0 + q * 32);
        ldsm4(ah1[q][0], ah1[q][1], ah1[q][2], ah1[q][3], aAddr1 + q * 32);
    }
#pragma unroll
    for (int k = 0; k < 12; ++k) {
        u32 al0[4], al1[4];
        const u32* a0p;
        const u32* a1p;
        if (k < 8) {
            a0p = ah0[k & 3]; a1p = ah1[k & 3];
        } else {
            ldsm4(al0[0], al0[1], al0[2], al0[3], aAddr0 + 128 + (k - 8) * 32);
            ldsm4(al1[0], al1[1], al1[2], al1[3], aAddr1 + 128 + (k - 8) * 32);
            a0p = al0; a1p = al1;
        }
#pragma unroll
        for (int jp = 0; jp < NT / 2; ++jp) {
            u32 b0, b1, b2, b3;
            ldsm4(b0, b1, b2, b3, bAddr + jp * 6400 + k * 32);
            mma16816(acc0[2 * jp],     a0p, b0, b1);
            mma16816(acc0[2 * jp + 1], a0p, b2, b3);
            mma16816(acc1[2 * jp],     a1p, b0, b1);
            mma16816(acc1[2 * jp + 1], a1p, b2, b3);
        }
    }
}

template<int NT>
static __device__ __forceinline__ void add_bias2(float (*a0)[4], float (*a1)[4],
                                                 const float* b, int lane) {
    const int ob = (lane & 3) * 2;
#pragma unroll
    for (int j = 0; j < NT; ++j) {
        float2 bb = *(const float2*)(b + 8 * j + ob);
        a0[j][0] += bb.x; a0[j][1] += bb.y; a0[j][2] += bb.x; a0[j][3] += bb.y;
        a1[j][0] += bb.x; a1[j][1] += bb.y; a1[j][2] += bb.x; a1[j][3] += bb.y;
    }
}
template<int NT>
static __device__ __forceinline__ void zero2(float (*a0)[4], float (*a1)[4]) {
#pragma unroll
    for (int j = 0; j < NT; ++j) {
        a0[j][0] = a0[j][1] = a0[j][2] = a0[j][3] = 0.0f;
        a1[j][0] = a1[j][1] = a1[j][2] = a1[j][3] = 0.0f;
    }
}

extern "C" __global__ void __launch_bounds__(128, 3)
nsf_tc(const float* __restrict__ x,
       const float* __restrict__ W_in, const float* __restrict__ b_in,
       const float* __restrict__ b_blk, const float* __restrict__ b_out,
       float* __restrict__ out, int n) {
    extern __shared__ char smem[];
    const u32 sb = smem_u32(smem);
    float* sWIN = (float*)(smem + SM_WIN);
    float* sBIN = (float*)(smem + SM_BIN);
    float* sBB  = (float*)(smem + SM_BB);
    float* sBO  = (float*)(smem + SM_BO);
    float* sCC  = (float*)(smem + SM_CC);

    const int tid = threadIdx.x, lane = tid & 31, w = tid >> 5;
    const int gidr = blockIdx.x * 128 + tid;
    const bool valid = gidr < n;
    const int g = valid ? gidr : (n - 1);

    float z0 = x[3 * g], z1 = x[3 * g + 1], z2 = x[3 * g + 2];
    float lad = 0.0f;

    for (int it = 0; it < 8; ++it) {
        __syncthreads();
        if (tid < 64) { sWIN[tid] = W_in[it * 64 + tid]; sBIN[tid] = b_in[it * 64 + tid]; }
        for (int i = tid; i < 256; i += 128) sBB[i] = b_blk[it * 256 + i];
        if (tid < 80) {
            float v = 0.0f;
            if (tid < 37) v = b_out[it * 74 + tid];
            else if (tid >= 40 && tid < 77) v = b_out[it * 74 + tid - 3];
            sBO[tid] = v;
        }
        float c = z2, t0 = z1, t1 = z0;    // reversed z
        sCC[tid] = c;
        stage_w(smem, g_wh + (it * 4 + 0) * 12288, 64, tid);
        __syncthreads();

        // h-init fragments for both M-tiles
        float hA0[8][4], hA1[8][4], tA0[10][4], tA1[10][4];
        {
            int r0 = 32 * w + (lane >> 2);
            float c00 = sCC[r0], c01 = sCC[r0 + 8];
            float c10 = sCC[r0 + 16], c11 = sCC[r0 + 24];
            const int ob = (lane & 3) * 2;
#pragma unroll
            for (int j = 0; j < 8; ++j) {
                int o = 8 * j + ob;
                float2 wi = *(const float2*)(sWIN + o);
                float2 bi = *(const float2*)(sBIN + o);
                hA0[j][0] = fmaf(c00, wi.x, bi.x); hA0[j][1] = fmaf(c00, wi.y, bi.y);
                hA0[j][2] = fmaf(c01, wi.x, bi.x); hA0[j][3] = fmaf(c01, wi.y, bi.y);
                hA1[j][0] = fmaf(c10, wi.x, bi.x); hA1[j][1] = fmaf(c10, wi.y, bi.y);
                hA1[j][2] = fmaf(c11, wi.x, bi.x); hA1[j][3] = fmaf(c11, wi.y, bi.y);
            }
        }
        // L1
        write_act2<8, true>(hA0, hA1, smem, w, lane);
        __syncwarp();
        zero2<8>(tA0, tA1);
        mma_layer2<8>(tA0, tA1, sb, w, lane);
        add_bias2<8>(tA0, tA1, sBB, lane);
        // L2 (acc = h)
        write_act2<8, true>(tA0, tA1, smem, w, lane);
        __syncthreads();
        stage_w(smem, g_wh + (it * 4 + 1) * 12288, 64, tid);
        __syncthreads();
        mma_layer2<8>(hA0, hA1, sb, w, lane);
        add_bias2<8>(hA0, hA1, sBB + 64, lane);
        // L3
        write_act2<8, true>(hA0, hA1, smem, w, lane);
        __syncthreads();
        stage_w(smem, g_wh + (it * 4 + 2) * 12288, 64, tid);
        __syncthreads();
        zero2<8>(tA0, tA1);
        mma_layer2<8>(tA0, tA1, sb, w, lane);
        add_bias2<8>(tA0, tA1, sBB + 128, lane);
        // L4 (acc = h)
        write_act2<8, true>(tA0, tA1, smem, w, lane);
        __syncthreads();
        stage_w(smem, g_wh + (it * 4 + 3) * 12288, 64, tid);
        __syncthreads();
        mma_layer2<8>(hA0, hA1, sb, w, lane);
        add_bias2<8>(hA0, hA1, sBB + 192, lane);
        // Out (N=80, no relu on input)
        write_act2<8, false>(hA0, hA1, smem, w, lane);
        __syncthreads();
        stage_w(smem, g_wo + it * 15360, 80, tid);
        __syncthreads();
        zero2<10>(tA0, tA1);
        mma_layer2<10>(tA0, tA1, sb, w, lane);
        add_bias2<10>(tA0, tA1, sBO, lane);
        __syncthreads();   // all mma reads done before exchange overwrites W+A panels

        // exchange params fp32 at base 0, 396-B pitch (conflict-free gather);
        // scalar stores (396 only 4-byte aligned on odd rows)
        {
            const int r0 = 32 * w + (lane >> 2);
            const int ob = (lane & 3) * 2;
#pragma unroll
            for (int t = 0; t < 4; ++t) {
                char* e = smem + (r0 + t * 8) * 396;
#pragma unroll
                for (int j = 0; j < 10; ++j) {
                    const float* f = (t < 2) ? tA0[j] : tA1[j];
                    int o4 = 4 * (8 * j + ob);
                    *(float*)(e + o4)     = f[(t & 1) * 2];
                    *(float*)(e + o4 + 4) = f[(t & 1) * 2 + 1];
                }
            }
        }
        __syncthreads();

        // splines: thread = point, both dims
        const char* row = smem + tid * 396;
        float y0, l0v, y1, l1v;
        {
            float p[37];
#pragma unroll
            for (int r = 0; r < 37; ++r) p[r] = *(const float*)(row + 4 * r);
            rq_spline(p, t0, y0, l0v);
        }
        {
            float p[37];
#pragma unroll
            for (int r = 0; r < 37; ++r) p[r] = *(const float*)(row + 4 * (40 + r));
            rq_spline(p, t1, y1, l1v);
        }
        z0 = c; z1 = y0; z2 = y1;
        lad += l0v + l1v;
    }

    if (valid)
        out[gidr] = fmaf(-0.5f, z0 * z0 + z1 * z1 + z2 * z2, LOGZc + lad);
}

extern "C" void kernel_launch(void* const* d_in, const int* in_sizes, int n_in,
                              void* d_out, int out_size) {
    const float* x     = (const float*)d_in[0];
    const float* W_in  = (const float*)d_in[1];
    const float* b_in  = (const float*)d_in[2];
    const float* W_blk = (const float*)d_in[3];
    const float* b_blk = (const float*)d_in[4];
    const float* W_out = (const float*)d_in[5];
    const float* b_out = (const float*)d_in[6];
    float* out = (float*)d_out;

    int n = in_sizes[0] / 3;
    conv_kernel<<<(8 * 4 * 64 * 192 + 8 * 80 * 192 + 255) / 256, 256>>>(W_blk, W_out);
    cudaFuncSetAttribute(nsf_tc, cudaFuncAttributeMaxDynamicSharedMemorySize, SMEM_BYTES);
    nsf_tc<<<(n + 127) / 128, 128, SMEM_BYTES>>>(x, W_in, b_in, b_blk, b_out, out, n);
}